// round 17
// baseline (speedup 1.0000x reference)
#include <cuda_runtime.h>
#include <cstdint>

// Problem constants
#define BATCH 16
#define SEQ   720
#define CIN   321
#define NORD  64
#define PRED  720
#define M_TOT (BATCH*CIN)        // 5136
#define MPAD  5376               // 84*64
#define TSPLIT 15
#define TCHUNK 48                // 720/15
#define ROW_STRIDE (SEQ*CIN)     // 231120
#define TSTRIDE 68               // buildk transpose stride
#define NCHAIN 32
#define OSTR  67
// k-paired layouts: per-t4 row holds (k,k+4) float2 pairs
#define KSTR2 144                // 64 cols * 2 + pad (mod 32 banks = 16)
#define KGRP  (4*KSTR2)          // 576 floats per 8-k group
#define ESTR2 272                // 128 cols * 2 + pad (mod 32 banks = 16)
#define EGRP  (4*ESTR2)          // 1088 floats per 8-k group

typedef unsigned long long ull;

// ---------------- helpers ----------------
__device__ __forceinline__ ull fma2(ull a, ull b, ull c) {
    ull d;
    asm("fma.rn.f32x2 %0, %1, %2, %3;" : "=l"(d) : "l"(a), "l"(b), "l"(c));
    return d;
}
__device__ __forceinline__ ull dup2(float x) {
    ull d; asm("mov.b64 %0, {%1, %1};" : "=l"(d) : "f"(x)); return d;
}
__device__ __forceinline__ float2 upk2(ull v) {
    float x, y; asm("mov.b64 {%0, %1}, %2;" : "=f"(x), "=f"(y) : "l"(v));
    return make_float2(x, y);
}
__device__ __forceinline__ float to_tf32(float x) {
    uint32_t r; asm("cvt.rna.tf32.f32 %0, %1;" : "=r"(r) : "f"(x));
    return __uint_as_float(r);
}
__device__ __forceinline__ void mma_tf32(float c[4],
    uint32_t a0, uint32_t a1, uint32_t a2, uint32_t a3,
    uint32_t b0, uint32_t b1) {
    asm volatile(
        "mma.sync.aligned.m16n8k8.row.col.f32.tf32.tf32.f32 "
        "{%0,%1,%2,%3}, {%4,%5,%6,%7}, {%8,%9}, {%0,%1,%2,%3};"
        : "+f"(c[0]), "+f"(c[1]), "+f"(c[2]), "+f"(c[3])
        : "r"(a0), "r"(a1), "r"(a2), "r"(a3), "r"(b0), "r"(b1));
}
#define U(v) __float_as_uint(v)

// ---------------- device scratch ----------------
__device__ float g_Kt   [PRED*NORD];        // pre-tf32
__device__ float g_Spart[NCHAIN*NORD];
__device__ float g_EWT  [NORD*PRED];        // (E@W)^T pre-tf32 : [n][p]
__device__ float g_eb   [PRED];
__device__ float g_XK   [TSPLIT][MPAD*NORD];
__device__ float g_XKpT [NORD*MPAD];        // alpha-folded pre-tf32: [n][m]
__device__ float g_rsum [TSPLIT][MPAD];
__device__ float g_rsq  [TSPLIT][MPAD];
__device__ float g_mean [MPAD];
__device__ float g_std  [MPAD];

// ============================================================================
// buildk (unchanged from R15)
// ============================================================================
__global__ void __launch_bounds__(256) buildk_kernel(
    const float* __restrict__ A, const float* __restrict__ Bv,
    const float* __restrict__ E, const float* __restrict__ W,
    const float* __restrict__ bm)
{
    extern __shared__ float sh[];
    const int tid = threadIdx.x;
    const int bid = blockIdx.x;

    if (bid >= NCHAIN) {
        float* Wsh = sh;
        float* Esh = sh + 4096;
        __shared__ float bsh[NORD];
        const int e = bid - NCHAIN;
        for (int i = tid; i < NORD*NORD; i += 256) Wsh[i] = W[i];
        for (int i = tid; i < 45*NORD; i += 256)  Esh[i] = E[e*45*NORD + i];
        if (tid < NORD) bsh[tid] = bm[tid];
        __syncthreads();
        for (int idx = tid; idx < 45*NORD; idx += 256) {
            const int pl = idx >> 6, m = idx & 63;
            float a0 = 0.f, a1 = 0.f;
#pragma unroll
            for (int n = 0; n < NORD; n += 2) {
                a0 += Esh[pl*NORD + n    ] * Wsh[(n    )*NORD + m];
                a1 += Esh[pl*NORD + n + 1] * Wsh[(n + 1)*NORD + m];
            }
            g_EWT[(size_t)m*PRED + e*45 + pl] = to_tf32(a0 + a1);
        }
        if (tid < 45) {
            float a = 0.f;
#pragma unroll
            for (int n = 0; n < NORD; n++) a += Esh[tid*NORD + n] * bsh[n];
            g_eb[e*45 + tid] = a;
        }
        return;
    }

    float* TP[6];
#pragma unroll
    for (int i = 0; i < 6; i++) TP[i] = sh + i * NORD * TSTRIDE;
    float* N0 = sh + 6 * NORD * TSTRIDE;
    float* N1 = N0 + NORD*NORD;
    __shared__ float vsh[NORD];
    __shared__ float pb[256];

    for (int i = tid; i < NORD*NORD; i += 256) N0[i] = A[i];
    __syncthreads();
    for (int i = tid; i < NORD*NORD; i += 256)
        TP[0][(i & 63)*TSTRIDE + (i >> 6)] = N0[i];
    __syncthreads();

    float* srcN = N0;
    float* dstN = N1;
    const int ig = tid >> 4;
    const int jg = tid & 15;
#pragma unroll
    for (int s = 0; s < 5; s++) {
        const float* srcT = TP[s];
        ull acc2[4][2];
#pragma unroll
        for (int ii = 0; ii < 4; ii++) { acc2[ii][0] = 0ull; acc2[ii][1] = 0ull; }
#pragma unroll 8
        for (int k = 0; k < NORD; k++) {
            const float4 a = *(const float4*)&srcT[k*TSTRIDE + ig*4];
            const ulonglong2 b = *(const ulonglong2*)&srcN[k*NORD + jg*4];
            float av[4] = {a.x, a.y, a.z, a.w};
#pragma unroll
            for (int ii = 0; ii < 4; ii++) {
                const ull am = dup2(av[ii]);
                acc2[ii][0] = fma2(am, b.x, acc2[ii][0]);
                acc2[ii][1] = fma2(am, b.y, acc2[ii][1]);
            }
        }
#pragma unroll
        for (int ii = 0; ii < 4; ii++) {
            const float2 lo = upk2(acc2[ii][0]);
            const float2 hi = upk2(acc2[ii][1]);
            float4 v; v.x = lo.x; v.y = lo.y; v.z = hi.x; v.w = hi.y;
            *(float4*)&dstN[(ig*4 + ii)*NORD + jg*4] = v;
        }
        __syncthreads();
        for (int i = tid; i < NORD*NORD; i += 256)
            TP[s+1][(i & 63)*TSTRIDE + (i >> 6)] = dstN[i];
        __syncthreads();
        float* tmp = srcN; srcN = dstN; dstN = tmp;
    }

    const int r = bid;
    const int n = tid & 63, q = tid >> 6;

    if (tid < NORD) vsh[tid] = Bv[tid];
    __syncthreads();
#pragma unroll
    for (int b = 0; b < 5; b++) {
        if ((r >> b) & 1) {
            float p = 0.f;
#pragma unroll
            for (int kk = 0; kk < 16; kk++) {
                const int k = q*16 + kk;
                p += TP[b][k*TSTRIDE + n] * vsh[k];
            }
            pb[tid] = p;
            __syncthreads();
            if (tid < NORD) vsh[tid] = pb[tid] + pb[tid+64] + pb[tid+128] + pb[tid+192];
            __syncthreads();
        }
    }

    const float* T32 = TP[5];
    float sacc = 0.f;
    for (int j = 0; j < 23; j++) {
        const int s_exp = 32*j + r;
        if (s_exp < 720 && tid < NORD) {
            const float u = vsh[tid];
            g_Kt[(719 - s_exp)*NORD + tid] = to_tf32(u);
            sacc += u;
        }
        if (j < 22) {
            float p = 0.f;
#pragma unroll
            for (int kk = 0; kk < 16; kk++) {
                const int k = q*16 + kk;
                p += T32[k*TSTRIDE + n] * vsh[k];
            }
            pb[tid] = p;
            __syncthreads();
            if (tid < NORD) vsh[tid] = pb[tid] + pb[tid+64] + pb[tid+128] + pb[tid+192];
            __syncthreads();
        }
    }
    if (tid < NORD) g_Spart[r*NORD + tid] = sacc;
}

// ============================================================================
// GEMM1 (tensor, k-paired smem): XK[m,n] = sum_t x[m,t]*Kt[t,n].
// grid (84, 15), block 128. Mtile=64, N=64, k-chunk 48 (6 groups of 8).
// Fragments fetched as float2 (k,k+4) pairs: 10 v2-LDS + 8 mma per group.
// ============================================================================
__global__ void __launch_bounds__(128) gemm1_kernel(const float* __restrict__ x) {
    __shared__ __align__(16) float Xs[6*KGRP];   // paired [g][t4][m*2+half]
    __shared__ __align__(16) float Ks[6*KGRP];   // paired [g][t4][n*2+half]
    __shared__ float sred[128], sqred[128];

    const int tid   = threadIdx.x;
    const int mbase = blockIdx.x * 64;
    const int h     = blockIdx.y;
    const int t0    = h * TCHUNK;

    const int ml   = tid & 63;
    const int trow = tid >> 6;           // 0/1
    const int m_load = mbase + ml;
    const int bidx   = m_load / CIN;
    const int chl    = m_load - bidx * CIN;
    const float* xrow = x + (size_t)bidx * ROW_STRIDE + chl;
    const bool mval   = (m_load < M_TOT);

    float psum = 0.f, psq = 0.f;
#pragma unroll 8
    for (int i = 0; i < TCHUNK/2; i++) {
        const int t = trow + 2*i;
        float xv = mval ? xrow[(size_t)(t0 + t) * CIN] : 0.f;
        psum += xv;
        psq  += xv * xv;
        const int g = t >> 3, r = t & 7;
        Xs[g*KGRP + (r & 3)*KSTR2 + ml*2 + (r >> 2)] = to_tf32(xv);
    }
    // Ks staging: 384 slots (6g x 4t4 x 16n4), pair rows (k, k+4)
#pragma unroll
    for (int i = 0; i < 3; i++) {
        const int idx = tid + i*128;
        const int g = idx >> 6, rem = idx & 63;
        const int t4 = rem >> 4, n4 = rem & 15;
        const int tA = t0 + g*8 + t4;
        const float4 a = *(const float4*)&g_Kt[tA*NORD + n4*4];
        const float4 b = *(const float4*)&g_Kt[(tA + 4)*NORD + n4*4];
        float* dst = &Ks[g*KGRP + t4*KSTR2 + n4*8];
        float4 v0; v0.x = a.x; v0.y = b.x; v0.z = a.y; v0.w = b.y;
        float4 v1; v1.x = a.z; v1.y = b.z; v1.z = a.w; v1.w = b.w;
        *(float4*)dst       = v0;
        *(float4*)(dst + 4) = v1;
    }
    __syncthreads();

    const int wid  = tid >> 5;
    const int lane = tid & 31;
    const int gid  = lane >> 2;
    const int tid4 = lane & 3;
    const int w16  = wid * 16;

    float c[8][4];
#pragma unroll
    for (int i = 0; i < 8; i++)
#pragma unroll
        for (int j = 0; j < 4; j++) c[i][j] = 0.f;

#pragma unroll
    for (int ks = 0; ks < 6; ks++) {
        const int abase = ks*KGRP + tid4*KSTR2;
        const float2 av0 = *(const float2*)&Xs[abase + (w16 + gid)*2];      // (a0,a2)
        const float2 av1 = *(const float2*)&Xs[abase + (w16 + gid + 8)*2];  // (a1,a3)
#pragma unroll
        for (int ns = 0; ns < 8; ns++) {
            const float2 bv = *(const float2*)&Ks[abase + (ns*8 + gid)*2];  // (b0,b1)
            mma_tf32(c[ns], U(av0.x), U(av1.x), U(av0.y), U(av1.y), U(bv.x), U(bv.y));
        }
    }

    float* xk = g_XK[h];
    const int row0 = mbase + w16 + gid;
#pragma unroll
    for (int ns = 0; ns < 8; ns++) {
        const int nc = ns*8 + 2*tid4;
        float2 v01; v01.x = c[ns][0]; v01.y = c[ns][1];
        float2 v23; v23.x = c[ns][2]; v23.y = c[ns][3];
        *(float2*)&xk[(size_t)row0 * NORD + nc]       = v01;
        *(float2*)&xk[(size_t)(row0+8) * NORD + nc]   = v23;
    }
    sred[tid]  = psum;
    sqred[tid] = psq;
    __syncthreads();
    if (tid < 64) {
        g_rsum[h][mbase + tid] = sred[tid] + sred[tid + 64];
        g_rsq [h][mbase + tid] = sqred[tid] + sqred[tid + 64];
    }
}

// ============================================================================
// fuse (unchanged from R15): partial reduce + stats + fold + transpose (tf32).
// ============================================================================
__global__ void __launch_bounds__(256) fuse_kernel(const float* __restrict__ aw,
                                                   const float* __restrict__ ab) {
    __shared__ float TT[64*65];
    __shared__ float alpha_s[64], beta_s[64], Ssh[64];
    const int tid = threadIdx.x;
    const int mb  = blockIdx.x * 64;

    if (tid < 64) {
        const int m = mb + tid;
        float s = 0.f, qq = 0.f;
#pragma unroll
        for (int h = 0; h < TSPLIT; h++) { s += g_rsum[h][m]; qq += g_rsq[h][m]; }
        const float mean = s * (1.0f / 720.0f);
        const float var  = qq * (1.0f / 720.0f) - mean * mean;
        const float sd   = sqrtf(var + 1e-5f);
        const int bidx = m / CIN;
        const int ch   = m - bidx * CIN;
        const float al = aw[ch] / sd;
        alpha_s[tid] = al;
        beta_s[tid]  = ab[ch] - mean * al;
        g_mean[m] = mean;
        g_std[m]  = sd;
    } else if (tid < 128) {
        const int nn = tid - 64;
        float s = 0.f;
#pragma unroll
        for (int rr = 0; rr < NCHAIN; rr++) s += g_Spart[rr*NORD + nn];
        Ssh[nn] = s;
    }
    __syncthreads();

#pragma unroll
    for (int i = 0; i < 16; i++) {
        const int idx = i*256 + tid;
        const int mlx = idx >> 6, nn = idx & 63;
        float v = 0.f;
#pragma unroll
        for (int h = 0; h < TSPLIT; h++) v += g_XK[h][(size_t)(mb + mlx)*NORD + nn];
        TT[nn*65 + mlx] = alpha_s[mlx]*v + beta_s[mlx]*Ssh[nn];
    }
    __syncthreads();
#pragma unroll
    for (int i = 0; i < 16; i++) {
        const int idx = i*256 + tid;
        const int nn = idx >> 6, mlx = idx & 63;
        g_XKpT[(size_t)nn*MPAD + mb + mlx] = to_tf32(TT[nn*65 + mlx]);
    }
}

// ============================================================================
// GEMM2 (tensor, k-paired smem) + epilogue. grid (84, 6), block 128.
// Mtile=64, Ptile=128, K=64 resident (8 groups of 8). Dynamic smem 53.25 KB.
// Per group: 2 a-v2 + 16 b-v2 LDS + 16 mma.
// ============================================================================
__global__ void __launch_bounds__(128) gemm2_kernel(float* __restrict__ out,
                                                    const float* __restrict__ aw,
                                                    const float* __restrict__ ab) {
    extern __shared__ float pool[];        // 8*KGRP + 8*EGRP = 4608+8704 = 13312
    float* Xs2 = pool;                     // paired [g][t4][m*2+half]
    float* Es  = pool + 8*KGRP;            // paired [g][t4][p*2+half]

    const int tid   = threadIdx.x;
    const int mbase = blockIdx.x * 64;
    const int pbase = blockIdx.y * 128;

    // stage Xs2: 512 slots (8g x 4t4 x 16m4)
#pragma unroll
    for (int i = 0; i < 4; i++) {
        const int idx = tid + i*128;
        const int g = idx >> 6, rem = idx & 63;
        const int t4 = rem >> 4, m4 = rem & 15;
        const int n = g*8 + t4;
        const float4 a = *(const float4*)&g_XKpT[(size_t)n*MPAD + mbase + m4*4];
        const float4 b = *(const float4*)&g_XKpT[(size_t)(n + 4)*MPAD + mbase + m4*4];
        float* dst = &Xs2[g*KGRP + t4*KSTR2 + m4*8];
        float4 v0; v0.x = a.x; v0.y = b.x; v0.z = a.y; v0.w = b.y;
        float4 v1; v1.x = a.z; v1.y = b.z; v1.z = a.w; v1.w = b.w;
        *(float4*)dst       = v0;
        *(float4*)(dst + 4) = v1;
    }
    // stage Es: 1024 slots (8g x 4t4 x 32p4), p guard
#pragma unroll
    for (int i = 0; i < 8; i++) {
        const int idx = tid + i*128;
        const int g = idx >> 7, rem = idx & 127;
        const int t4 = rem >> 5, p4 = rem & 31;
        const int n = g*8 + t4;
        const int p = pbase + p4*4;
        float4 a = make_float4(0.f, 0.f, 0.f, 0.f);
        float4 b = make_float4(0.f, 0.f, 0.f, 0.f);
        if (p < PRED) {
            a = *(const float4*)&g_EWT[(size_t)n*PRED + p];
            b = *(const float4*)&g_EWT[(size_t)(n + 4)*PRED + p];
        }
        float* dst = &Es[g*EGRP + t4*ESTR2 + p4*8];
        float4 v0; v0.x = a.x; v0.y = b.x; v0.z = a.y; v0.w = b.y;
        float4 v1; v1.x = a.z; v1.y = b.z; v1.z = a.w; v1.w = b.w;
        *(float4*)dst       = v0;
        *(float4*)(dst + 4) = v1;
    }
    __syncthreads();

    const int wid  = tid >> 5;
    const int lane = tid & 31;
    const int gid  = lane >> 2;
    const int tid4 = lane & 3;
    const int w16  = wid * 16;

    float c[16][4];
#pragma unroll
    for (int i = 0; i < 16; i++)
#pragma unroll
        for (int j = 0; j < 4; j++) c[i][j] = 0.f;

#pragma unroll
    for (int ks = 0; ks < 8; ks++) {
        const int abase = ks*KGRP + tid4*KSTR2;
        const int bbase = ks*EGRP + tid4*ESTR2;
        const float2 av0 = *(const float2*)&Xs2[abase + (w16 + gid)*2];
        const float2 av1 = *(const float2*)&Xs2[abase + (w16 + gid + 8)*2];
#pragma unroll
        for (int ps = 0; ps < 16; ps++) {
            const float2 bv = *(const float2*)&Es[bbase + (ps*8 + gid)*2];
            mma_tf32(c[ps], U(av0.x), U(av1.x), U(av0.y), U(av1.y), U(bv.x), U(bv.y));
        }
    }
    __syncthreads();   // pool reused as Os

    // epilogue: stage into Os[p_loc][m_loc] (stride 67): 128*67 = 8576 floats
    float* Os = pool;
    const int m0 = mbase + w16 + gid;
    const int m1 = m0 + 8;
    const float mean0 = g_mean[m0], sd0 = g_std[m0];
    const float mean1 = g_mean[m1], sd1 = g_std[m1];
    const int bi0 = m0 / CIN, ch0 = m0 - bi0*CIN;
    const int bi1 = m1 / CIN, ch1 = m1 - bi1*CIN;
    const float ab0 = ab[ch0], sc0 = sd0 / (aw[ch0] + 1e-10f);
    const float ab1 = ab[ch1], sc1 = sd1 / (aw[ch1] + 1e-10f);
    const int mloc0 = w16 + gid;

#pragma unroll
    for (int ps = 0; ps < 16; ps++) {
        const int pl0 = ps*8 + 2*tid4;
        const int p0  = pbase + pl0;
        const float e0 = (p0     < PRED) ? g_eb[p0]     : 0.f;
        const float e1 = (p0 + 1 < PRED) ? g_eb[p0 + 1] : 0.f;
        Os[(pl0    )*OSTR + mloc0    ] = (c[ps][0] + e0 - ab0) * sc0 + mean0;
        Os[(pl0 + 1)*OSTR + mloc0    ] = (c[ps][1] + e1 - ab0) * sc0 + mean0;
        Os[(pl0    )*OSTR + mloc0 + 8] = (c[ps][2] + e0 - ab1) * sc1 + mean1;
        Os[(pl0 + 1)*OSTR + mloc0 + 8] = (c[ps][3] + e1 - ab1) * sc1 + mean1;
    }
    __syncthreads();

    // coalesced global store: 64 lanes sweep m, two phases sweep p
    const int mls = tid & 63;
    const int ph  = tid >> 6;            // 0/1
    const int m   = mbase + mls;
    if (m < M_TOT) {
        const int bi = m / CIN;
        const int ch = m - bi * CIN;
        float* ob = out + (size_t)bi * ROW_STRIDE + ch;
        const int plim = (PRED - pbase < 128) ? (PRED - pbase) : 128;
        for (int pl = ph; pl < plim; pl += 2)
            ob[(size_t)(pbase + pl) * CIN] = Os[pl*OSTR + mls];
    }
}

// ---------------- launcher: 4 graph nodes ----------------
extern "C" void kernel_launch(void* const* d_in, const int* in_sizes, int n_in,
                              void* d_out, int out_size) {
    (void)in_sizes; (void)n_in; (void)out_size;
    const float* x  = (const float*)d_in[0];   // x_enc (16,720,321)
    const float* A  = (const float*)d_in[1];   // A (64,64)
    const float* Bv = (const float*)d_in[2];   // B_vec (64)
    const float* E  = (const float*)d_in[3];   // eval_matrix (720,64)
    const float* W  = (const float*)d_in[4];   // W_mlp (64,64)
    const float* bm = (const float*)d_in[5];   // b_mlp (64)
    const float* aw = (const float*)d_in[6];   // affine_weight (321)
    const float* ab = (const float*)d_in[7];   // affine_bias (321)
    float* out = (float*)d_out;

    const int buildk_smem = (6*NORD*TSTRIDE + 2*NORD*NORD) * (int)sizeof(float); // 137216
    cudaFuncSetAttribute(buildk_kernel, cudaFuncAttributeMaxDynamicSharedMemorySize, buildk_smem);
    const int gemm2_smem = (8*KGRP + 8*EGRP) * (int)sizeof(float);               // 53248
    cudaFuncSetAttribute(gemm2_kernel, cudaFuncAttributeMaxDynamicSharedMemorySize, gemm2_smem);

    buildk_kernel<<<NCHAIN + 16, 256, buildk_smem>>>(A, Bv, E, W, bm);
    gemm1_kernel<<<dim3(MPAD/64, TSPLIT), 128>>>(x);
    fuse_kernel<<<MPAD/64, 256>>>(aw, ab);
    gemm2_kernel<<<dim3(MPAD/64, 6), 128, gemm2_smem>>>(out, aw, ab);
}